// round 2
// baseline (speedup 1.0000x reference)
#include <cuda_runtime.h>
#include <cuda_bf16.h>
#include <cstdint>

#define NN 100000
#define EE 1250000
#define DD 64
#define SCAN_T 1024

// ---------------------------------------------------------------------------
// Scratch (__device__ globals; no allocation allowed)
// ---------------------------------------------------------------------------
__device__ float g_deg[NN];          // weighted degree accum
__device__ float g_dis[NN];          // deg^{-1/2}
__device__ int   g_cnt[NN];          // edge count per dst
__device__ int   g_fill[NN];         // fill cursor during reorder
__device__ int   g_rowptr[NN + 1];   // CSR row pointers (by dst)
__device__ int2  g_epair[EE];        // per-edge (src, coef-bits), dst-grouped
__device__ float g_h[NN * DD];       // feature buffer A
__device__ float g_agg[NN * DD];     // feature buffer B

// ---------------------------------------------------------------------------
// Zero deg / cnt / fill
// ---------------------------------------------------------------------------
__global__ void k_zero() {
    int i = blockIdx.x * blockDim.x + threadIdx.x;
    if (i < NN) { g_deg[i] = 0.0f; g_cnt[i] = 0; g_fill[i] = 0; }
}

// Histogram: weighted degree + edge count per dst
__global__ void k_hist(const int* __restrict__ dst, const float* __restrict__ w) {
    int e = blockIdx.x * blockDim.x + threadIdx.x;
    if (e < EE) {
        int d = dst[e];
        atomicAdd(&g_deg[d], w[e]);
        atomicAdd(&g_cnt[d], 1);
    }
}

__global__ void k_dis() {
    int i = blockIdx.x * blockDim.x + threadIdx.x;
    if (i < NN) g_dis[i] = rsqrtf(g_deg[i] + 1.0f);
}

// Single-block exclusive scan of g_cnt -> g_rowptr (NN elements + total)
__global__ void k_scan() {
    __shared__ int sh[SCAN_T];
    const int chunk = (NN + SCAN_T - 1) / SCAN_T;   // 98
    int t = threadIdx.x;
    int beg = t * chunk;
    int end = beg + chunk; if (end > NN) end = NN;

    int s = 0;
    for (int i = beg; i < end; i++) s += g_cnt[i];
    sh[t] = s;
    __syncthreads();

    // Hillis-Steele inclusive scan
    for (int off = 1; off < SCAN_T; off <<= 1) {
        int v = (t >= off) ? sh[t - off] : 0;
        __syncthreads();
        sh[t] += v;
        __syncthreads();
    }

    int run = (t == 0) ? 0 : sh[t - 1];   // exclusive base for this thread
    for (int i = beg; i < end; i++) {
        g_rowptr[i] = run;
        run += g_cnt[i];
    }
    if (t == 0) g_rowptr[NN] = sh[SCAN_T - 1];
}

// Reorder edges into CSR slots; fuse coef computation
__global__ void k_reorder(const int* __restrict__ src, const int* __restrict__ dst,
                          const float* __restrict__ w) {
    int e = blockIdx.x * blockDim.x + threadIdx.x;
    if (e >= EE) return;
    int s = src[e];
    int d = dst[e];
    float coef = g_dis[s] * w[e] * g_dis[d];
    int pos = g_rowptr[d] + atomicAdd(&g_fill[d], 1);
    g_epair[pos] = make_int2(s, __float_as_int(coef));
}

// ---------------------------------------------------------------------------
// GEMM: H[n][o] = sum_k X[n][k] * W[o][k]
// 256 threads/block, 32 rows/block, 8 output cols/thread.
// ---------------------------------------------------------------------------
__global__ void k_gemm(const float* __restrict__ X, const float* __restrict__ W,
                       float* __restrict__ H) {
    __shared__ float Ws[DD][DD];      // Ws[k][o] = W[o][k]
    __shared__ float Xs[32][DD + 1];

    int tid = threadIdx.x;
    int row0 = blockIdx.x * 32;

    for (int idx = tid; idx < DD * DD; idx += 256) {
        int o = idx / DD, k = idx % DD;
        Ws[k][o] = W[o * DD + k];
    }
    for (int idx = tid; idx < 32 * DD; idx += 256) {
        int r = idx / DD, k = idx % DD;
        Xs[r][k] = X[(size_t)(row0 + r) * DD + k];
    }
    __syncthreads();

    int r = tid >> 3;
    int j = (tid & 7) * 8;

    float acc[8];
#pragma unroll
    for (int i = 0; i < 8; i++) acc[i] = 0.0f;

#pragma unroll 8
    for (int k = 0; k < DD; k++) {
        float xv = Xs[r][k];
        float4 w0 = *reinterpret_cast<const float4*>(&Ws[k][j]);
        float4 w1 = *reinterpret_cast<const float4*>(&Ws[k][j + 4]);
        acc[0] = fmaf(xv, w0.x, acc[0]);
        acc[1] = fmaf(xv, w0.y, acc[1]);
        acc[2] = fmaf(xv, w0.z, acc[2]);
        acc[3] = fmaf(xv, w0.w, acc[3]);
        acc[4] = fmaf(xv, w1.x, acc[4]);
        acc[5] = fmaf(xv, w1.y, acc[5]);
        acc[6] = fmaf(xv, w1.z, acc[6]);
        acc[7] = fmaf(xv, w1.w, acc[7]);
    }

    float* hp = H + (size_t)(row0 + r) * DD + j;
    *reinterpret_cast<float4*>(hp)     = make_float4(acc[0], acc[1], acc[2], acc[3]);
    *reinterpret_cast<float4*>(hp + 4) = make_float4(acc[4], acc[5], acc[6], acc[7]);
}

// ---------------------------------------------------------------------------
// CSR gather: OUT[n] = sum_e coef*H[src] + H[n]*dis[n]^2 + b  (+ optional relu)
// One warp per node; lane handles dims [2*lane, 2*lane+1].
// ---------------------------------------------------------------------------
__global__ void k_gather(const float* __restrict__ H, float* __restrict__ OUT,
                         const float* __restrict__ b, int do_relu) {
    int warp = (blockIdx.x * blockDim.x + threadIdx.x) >> 5;
    if (warp >= NN) return;
    int lane = threadIdx.x & 31;
    int n = warp;

    int beg = g_rowptr[n];
    int end = g_rowptr[n + 1];

    float2 acc0 = make_float2(0.0f, 0.0f);
    float2 acc1 = make_float2(0.0f, 0.0f);

    int e = beg;
    for (; e + 2 <= end; e += 2) {
        int2 p0 = g_epair[e];
        int2 p1 = g_epair[e + 1];
        float2 v0 = *(reinterpret_cast<const float2*>(H + ((size_t)p0.x << 6)) + lane);
        float2 v1 = *(reinterpret_cast<const float2*>(H + ((size_t)p1.x << 6)) + lane);
        float c0 = __int_as_float(p0.y);
        float c1 = __int_as_float(p1.y);
        acc0.x = fmaf(c0, v0.x, acc0.x);
        acc0.y = fmaf(c0, v0.y, acc0.y);
        acc1.x = fmaf(c1, v1.x, acc1.x);
        acc1.y = fmaf(c1, v1.y, acc1.y);
    }
    if (e < end) {
        int2 p0 = g_epair[e];
        float2 v0 = *(reinterpret_cast<const float2*>(H + ((size_t)p0.x << 6)) + lane);
        float c0 = __int_as_float(p0.y);
        acc0.x = fmaf(c0, v0.x, acc0.x);
        acc0.y = fmaf(c0, v0.y, acc0.y);
    }

    float s = g_dis[n];
    s = s * s;
    float2 hs = *(reinterpret_cast<const float2*>(H + ((size_t)n << 6)) + lane);
    float2 bv = *(reinterpret_cast<const float2*>(b) + lane);

    float ox = acc0.x + acc1.x + hs.x * s + bv.x;
    float oy = acc0.y + acc1.y + hs.y * s + bv.y;
    if (do_relu) {
        ox = fmaxf(ox, 0.0f);
        oy = fmaxf(oy, 0.0f);
    }
    *(reinterpret_cast<float2*>(OUT + ((size_t)n << 6)) + lane) = make_float2(ox, oy);
}

// ---------------------------------------------------------------------------
// Launch
// Inputs: 0:x [N,64] f32, 1:edge_index [2,E] i32, 2:edge_weight [E] f32,
//         3:W1, 4:b1, 5:W2, 6:b2   Output: [N,64] f32
// ---------------------------------------------------------------------------
extern "C" void kernel_launch(void* const* d_in, const int* in_sizes, int n_in,
                              void* d_out, int out_size) {
    const float* x  = (const float*)d_in[0];
    const int*   ei = (const int*)d_in[1];
    const float* w  = (const float*)d_in[2];
    const float* W1 = (const float*)d_in[3];
    const float* b1 = (const float*)d_in[4];
    const float* W2 = (const float*)d_in[5];
    const float* b2 = (const float*)d_in[6];
    float* out = (float*)d_out;

    const int* src = ei;
    const int* dst = ei + EE;

    float* h_p;   cudaGetSymbolAddress((void**)&h_p,   g_h);
    float* agg_p; cudaGetSymbolAddress((void**)&agg_p, g_agg);

    const int T = 256;
    int bN = (NN + T - 1) / T;
    int bE = (EE + T - 1) / T;
    int bG = NN / 32;                        // 3125
    int bW = (NN * 32 + T - 1) / T;          // warp-per-node gather: 12500

    // CSR build (shared by both layers)
    k_zero<<<bN, T>>>();
    k_hist<<<bE, T>>>(dst, w);
    k_dis<<<bN, T>>>();
    k_scan<<<1, SCAN_T>>>();
    k_reorder<<<bE, T>>>(src, dst, w);

    // layer 1: x @ W1^T -> h, gather -> agg (with relu)
    k_gemm<<<bG, T>>>(x, W1, h_p);
    k_gather<<<bW, T>>>(h_p, agg_p, b1, 1);

    // layer 2: agg @ W2^T -> h, gather -> out
    k_gemm<<<bG, T>>>(agg_p, W2, h_p);
    k_gather<<<bW, T>>>(h_p, out, b2, 0);
}

// round 3
// speedup vs baseline: 1.1212x; 1.1212x over previous
#include <cuda_runtime.h>
#include <cuda_bf16.h>
#include <cstdint>

#define NN 100000
#define EE 1250000
#define DD 64
#define NB ((NN + 255) / 256)   // 391 scan blocks

// ---------------------------------------------------------------------------
// Scratch (__device__ globals; no allocation allowed)
// ---------------------------------------------------------------------------
__device__ float g_deg[NN];          // weighted degree accum
__device__ float g_dis[NN];          // deg^{-1/2}
__device__ int   g_cnt[NN];          // edge count per dst
__device__ int   g_fill[NN];         // fill cursor during reorder
__device__ int   g_rowptr[NN + 1];   // CSR row pointers (by dst)
__device__ int   g_bsum[NB];         // per-block scan partials
__device__ int2  g_epair[EE];        // per-edge (src, coef-bits), dst-grouped
__device__ float g_h[NN * DD];       // feature buffer A
__device__ float g_agg[NN * DD];     // feature buffer B

// ---------------------------------------------------------------------------
// Zero deg / cnt / fill
// ---------------------------------------------------------------------------
__global__ void k_zero() {
    int i = blockIdx.x * blockDim.x + threadIdx.x;
    if (i < NN) { g_deg[i] = 0.0f; g_cnt[i] = 0; g_fill[i] = 0; }
}

// Histogram: weighted degree + edge count per dst
__global__ void k_hist(const int* __restrict__ dst, const float* __restrict__ w) {
    int e = blockIdx.x * blockDim.x + threadIdx.x;
    if (e < EE) {
        int d = dst[e];
        atomicAdd(&g_deg[d], w[e]);
        atomicAdd(&g_cnt[d], 1);
    }
}

__global__ void k_dis() {
    int i = blockIdx.x * blockDim.x + threadIdx.x;
    if (i < NN) g_dis[i] = rsqrtf(g_deg[i] + 1.0f);
}

// ---------------------------------------------------------------------------
// Multi-block exclusive scan of g_cnt -> g_rowptr
// Phase 1: per-block exclusive scan + block totals
// ---------------------------------------------------------------------------
__global__ void k_scan1() {
    __shared__ int sh[256];
    int t = threadIdx.x;
    int i = blockIdx.x * 256 + t;
    int v = (i < NN) ? g_cnt[i] : 0;
    sh[t] = v;
    __syncthreads();
    for (int off = 1; off < 256; off <<= 1) {
        int u = (t >= off) ? sh[t - off] : 0;
        __syncthreads();
        sh[t] += u;
        __syncthreads();
    }
    if (i < NN) g_rowptr[i] = sh[t] - v;        // exclusive within block
    if (t == 255) g_bsum[blockIdx.x] = sh[255]; // block total
}

// Phase 2: single-block exclusive scan of 391 block totals
__global__ void k_scan2() {
    __shared__ int sh[512];
    int t = threadIdx.x;
    int v = (t < NB) ? g_bsum[t] : 0;
    sh[t] = v;
    __syncthreads();
    for (int off = 1; off < 512; off <<= 1) {
        int u = (t >= off) ? sh[t - off] : 0;
        __syncthreads();
        sh[t] += u;
        __syncthreads();
    }
    if (t < NB) g_bsum[t] = sh[t] - v;          // exclusive block offset
}

// Phase 3: add block offsets
__global__ void k_scan3() {
    int i = blockIdx.x * 256 + threadIdx.x;
    if (i < NN) g_rowptr[i] += g_bsum[blockIdx.x];
    if (i == 0) g_rowptr[NN] = EE;
}

// Reorder edges into CSR slots; fuse coef computation
__global__ void k_reorder(const int* __restrict__ src, const int* __restrict__ dst,
                          const float* __restrict__ w) {
    int e = blockIdx.x * blockDim.x + threadIdx.x;
    if (e >= EE) return;
    int s = src[e];
    int d = dst[e];
    float coef = g_dis[s] * w[e] * g_dis[d];
    int pos = g_rowptr[d] + atomicAdd(&g_fill[d], 1);
    g_epair[pos] = make_int2(s, __float_as_int(coef));
}

// ---------------------------------------------------------------------------
// GEMM: H[n][o] = sum_k X[n][k] * W[o][k]
// ---------------------------------------------------------------------------
__global__ void k_gemm(const float* __restrict__ X, const float* __restrict__ W,
                       float* __restrict__ H) {
    __shared__ float Ws[DD][DD];      // Ws[k][o] = W[o][k]
    __shared__ float Xs[32][DD + 1];

    int tid = threadIdx.x;
    int row0 = blockIdx.x * 32;

    for (int idx = tid; idx < DD * DD; idx += 256) {
        int o = idx / DD, k = idx % DD;
        Ws[k][o] = W[o * DD + k];
    }
    for (int idx = tid; idx < 32 * DD; idx += 256) {
        int r = idx / DD, k = idx % DD;
        Xs[r][k] = X[(size_t)(row0 + r) * DD + k];
    }
    __syncthreads();

    int r = tid >> 3;
    int j = (tid & 7) * 8;

    float acc[8];
#pragma unroll
    for (int i = 0; i < 8; i++) acc[i] = 0.0f;

#pragma unroll 8
    for (int k = 0; k < DD; k++) {
        float xv = Xs[r][k];
        float4 w0 = *reinterpret_cast<const float4*>(&Ws[k][j]);
        float4 w1 = *reinterpret_cast<const float4*>(&Ws[k][j + 4]);
        acc[0] = fmaf(xv, w0.x, acc[0]);
        acc[1] = fmaf(xv, w0.y, acc[1]);
        acc[2] = fmaf(xv, w0.z, acc[2]);
        acc[3] = fmaf(xv, w0.w, acc[3]);
        acc[4] = fmaf(xv, w1.x, acc[4]);
        acc[5] = fmaf(xv, w1.y, acc[5]);
        acc[6] = fmaf(xv, w1.z, acc[6]);
        acc[7] = fmaf(xv, w1.w, acc[7]);
    }

    float* hp = H + (size_t)(row0 + r) * DD + j;
    *reinterpret_cast<float4*>(hp)     = make_float4(acc[0], acc[1], acc[2], acc[3]);
    *reinterpret_cast<float4*>(hp + 4) = make_float4(acc[4], acc[5], acc[6], acc[7]);
}

// ---------------------------------------------------------------------------
// CSR gather: OUT[n] = sum_e coef*H[src] + H[n]*dis[n]^2 + b  (+ optional relu)
// TWO warps per node: warp-half h covers dims [h*32, h*32+32), 1 float/lane.
// 4-edge unroll: 4 independent index loads, then 4 independent feature loads.
// ---------------------------------------------------------------------------
__global__ void k_gather(const float* __restrict__ H, float* __restrict__ OUT,
                         const float* __restrict__ b, int do_relu) {
    int gw = (blockIdx.x * blockDim.x + threadIdx.x) >> 5;   // global warp id
    int n = gw >> 1;
    if (n >= NN) return;
    int lane = threadIdx.x & 31;
    int c = ((gw & 1) << 5) + lane;                          // dim 0..63

    int beg = g_rowptr[n];
    int end = g_rowptr[n + 1];

    float a0 = 0.0f, a1 = 0.0f, a2 = 0.0f, a3 = 0.0f;

    int e = beg;
    for (; e + 4 <= end; e += 4) {
        int2 p0 = g_epair[e];
        int2 p1 = g_epair[e + 1];
        int2 p2 = g_epair[e + 2];
        int2 p3 = g_epair[e + 3];
        float v0 = __ldg(H + ((size_t)p0.x << 6) + c);
        float v1 = __ldg(H + ((size_t)p1.x << 6) + c);
        float v2 = __ldg(H + ((size_t)p2.x << 6) + c);
        float v3 = __ldg(H + ((size_t)p3.x << 6) + c);
        a0 = fmaf(__int_as_float(p0.y), v0, a0);
        a1 = fmaf(__int_as_float(p1.y), v1, a1);
        a2 = fmaf(__int_as_float(p2.y), v2, a2);
        a3 = fmaf(__int_as_float(p3.y), v3, a3);
    }
    for (; e < end; e++) {
        int2 p = g_epair[e];
        a0 = fmaf(__int_as_float(p.y), __ldg(H + ((size_t)p.x << 6) + c), a0);
    }

    float s = g_dis[n];
    s = s * s;
    float o = (a0 + a1) + (a2 + a3)
            + __ldg(H + ((size_t)n << 6) + c) * s + b[c];
    if (do_relu) o = fmaxf(o, 0.0f);
    OUT[((size_t)n << 6) + c] = o;
}

// ---------------------------------------------------------------------------
// Launch
// Inputs: 0:x [N,64] f32, 1:edge_index [2,E] i32, 2:edge_weight [E] f32,
//         3:W1, 4:b1, 5:W2, 6:b2   Output: [N,64] f32
// ---------------------------------------------------------------------------
extern "C" void kernel_launch(void* const* d_in, const int* in_sizes, int n_in,
                              void* d_out, int out_size) {
    const float* x  = (const float*)d_in[0];
    const int*   ei = (const int*)d_in[1];
    const float* w  = (const float*)d_in[2];
    const float* W1 = (const float*)d_in[3];
    const float* b1 = (const float*)d_in[4];
    const float* W2 = (const float*)d_in[5];
    const float* b2 = (const float*)d_in[6];
    float* out = (float*)d_out;

    const int* src = ei;
    const int* dst = ei + EE;

    float* h_p;   cudaGetSymbolAddress((void**)&h_p,   g_h);
    float* agg_p; cudaGetSymbolAddress((void**)&agg_p, g_agg);

    const int T = 256;
    int bN = (NN + T - 1) / T;                 // 391
    int bE = (EE + T - 1) / T;                 // 4883
    int bG = NN / 32;                          // 3125
    int bW = (NN * 2 * 32 + T - 1) / T;        // 2 warps/node: 25000

    // CSR build (shared by both layers)
    k_zero<<<bN, T>>>();
    k_hist<<<bE, T>>>(dst, w);
    k_dis<<<bN, T>>>();
    k_scan1<<<NB, 256>>>();
    k_scan2<<<1, 512>>>();
    k_scan3<<<NB, 256>>>();
    k_reorder<<<bE, T>>>(src, dst, w);

    // layer 1: x @ W1^T -> h, gather -> agg (with relu)
    k_gemm<<<bG, T>>>(x, W1, h_p);
    k_gather<<<bW, T>>>(h_p, agg_p, b1, 1);

    // layer 2: agg @ W2^T -> h, gather -> out
    k_gemm<<<bG, T>>>(agg_p, W2, h_p);
    k_gather<<<bW, T>>>(h_p, out, b2, 0);
}

// round 4
// speedup vs baseline: 1.1310x; 1.0088x over previous
#include <cuda_runtime.h>
#include <cuda_bf16.h>
#include <cstdint>

#define NN 100000
#define EE 1250000
#define DD 64
#define BB 391            // build-kernel blocks (391*256 = 100096 >= NN)
#define BT 256            // build-kernel threads

// ---------------------------------------------------------------------------
// Scratch (__device__ globals; no allocation allowed)
// ---------------------------------------------------------------------------
__device__ unsigned long long g_pack[NN];  // [63:48] count, [45:0] fixed-point deg (zeroed in-kernel each run)
__device__ float g_dis[NN];                // deg^{-1/2}
__device__ int   g_rowptr[NN];             // scan-> start ptr, reorder-> end ptr (rebuilt each run)
__device__ int   g_bsum[BB];               // per-block scan partials
__device__ int2  g_epair[EE];              // (src, coef-bits), dst-grouped
__device__ float g_h[NN * DD];             // feature buffer A
__device__ float g_agg[NN * DD];           // feature buffer B
__device__ unsigned g_barcnt;              // grid barrier arrival counter (self-resetting)
__device__ unsigned g_bargen;              // grid barrier generation (monotonic)
__device__ int g_dummy;

// ---------------------------------------------------------------------------
__global__ void k_dummy() { if (threadIdx.x == 0) g_dummy = 1; }

// ---------------------------------------------------------------------------
// Fused CSR build: hist -> (dis, local scan) -> offsets/rowptr -> reorder
// All BB blocks co-resident; grid barriers via atomic generation counter.
// ---------------------------------------------------------------------------
__device__ __forceinline__ void grid_bar(unsigned base, unsigned k) {
    __syncthreads();
    if (threadIdx.x == 0) {
        __threadfence();
        unsigned t = atomicAdd(&g_barcnt, 1u);
        if (t == BB - 1) {
            g_barcnt = 0;
            __threadfence();
            atomicAdd(&g_bargen, 1u);
        } else {
            while (atomicAdd(&g_bargen, 0u) - base < k) { }
        }
        __threadfence();
    }
    __syncthreads();
}

__global__ void __launch_bounds__(BT) k_build(const int* __restrict__ src,
                                              const int* __restrict__ dst,
                                              const float* __restrict__ w) {
    __shared__ int sh[BT];
    __shared__ unsigned s_base;
    __shared__ int s_off;

    int t = threadIdx.x;
    int bid = blockIdx.x;
    if (t == 0) s_base = atomicAdd(&g_bargen, 0u);
    __syncthreads();
    unsigned base = s_base;

    // --- phase 1: histogram (1 packed u64 atomic per edge) ---
    for (int e = bid * BT + t; e < EE; e += BB * BT) {
        int d = dst[e];
        unsigned long long enc = (unsigned long long)(w[e] * 1099511627776.0f)  // w * 2^40
                               | (1ULL << 48);
        atomicAdd(&g_pack[d], enc);
    }
    grid_bar(base, 1);

    // --- phase 2: per-node dis + local scan + block totals; clear pack ---
    int i = bid * BT + t;
    int cnt = 0;
    if (i < NN) {
        unsigned long long p = g_pack[i];
        g_pack[i] = 0ULL;  // restore for next replay
        cnt = (int)(p >> 48);
        float deg = (float)(p & ((1ULL << 48) - 1ULL)) * (1.0f / 1099511627776.0f);
        g_dis[i] = rsqrtf(deg + 1.0f);
    }
    sh[t] = cnt;
    __syncthreads();
    for (int off = 1; off < BT; off <<= 1) {
        int u = (t >= off) ? sh[t - off] : 0;
        __syncthreads();
        sh[t] += u;
        __syncthreads();
    }
    int local_excl = sh[t] - cnt;
    if (t == BT - 1) g_bsum[bid] = sh[BT - 1];
    grid_bar(base, 2);

    // --- phase 3: block offset = sum of g_bsum[0..bid); write rowptr starts ---
    {
        int s = 0;
        if (t < bid) s += g_bsum[t];
        if (t + BT < bid) s += g_bsum[t + BT];
        __syncthreads();           // sh reuse safe
        sh[t] = s;
        __syncthreads();
        for (int off2 = BT / 2; off2 > 0; off2 >>= 1) {
            if (t < off2) sh[t] += sh[t + off2];
            __syncthreads();
        }
        if (t == 0) s_off = sh[0];
        __syncthreads();
    }
    if (i < NN) g_rowptr[i] = s_off + local_excl;   // start pointer (becomes end after fill)
    grid_bar(base, 3);

    // --- phase 4: reorder edges into CSR slots (rowptr as cursor) ---
    for (int e = bid * BT + t; e < EE; e += BB * BT) {
        int s = src[e];
        int d = dst[e];
        float coef = g_dis[s] * w[e] * g_dis[d];
        int pos = atomicAdd(&g_rowptr[d], 1);
        g_epair[pos] = make_int2(s, __float_as_int(coef));
    }
}

// ---------------------------------------------------------------------------
// GEMM: H[n][o] = sum_k X[n][k] * W[o][k]
// ---------------------------------------------------------------------------
__global__ void k_gemm(const float* __restrict__ X, const float* __restrict__ W,
                       float* __restrict__ H) {
    __shared__ float Ws[DD][DD];      // Ws[k][o] = W[o][k]
    __shared__ float Xs[32][DD + 1];

    int tid = threadIdx.x;
    int row0 = blockIdx.x * 32;

    for (int idx = tid; idx < DD * DD; idx += 256) {
        int o = idx / DD, k = idx % DD;
        Ws[k][o] = W[o * DD + k];
    }
    for (int idx = tid; idx < 32 * DD; idx += 256) {
        int r = idx / DD, k = idx % DD;
        Xs[r][k] = X[(size_t)(row0 + r) * DD + k];
    }
    __syncthreads();

    int r = tid >> 3;
    int j = (tid & 7) * 8;

    float acc[8];
#pragma unroll
    for (int i = 0; i < 8; i++) acc[i] = 0.0f;

#pragma unroll 8
    for (int k = 0; k < DD; k++) {
        float xv = Xs[r][k];
        float4 w0 = *reinterpret_cast<const float4*>(&Ws[k][j]);
        float4 w1 = *reinterpret_cast<const float4*>(&Ws[k][j + 4]);
        acc[0] = fmaf(xv, w0.x, acc[0]);
        acc[1] = fmaf(xv, w0.y, acc[1]);
        acc[2] = fmaf(xv, w0.z, acc[2]);
        acc[3] = fmaf(xv, w0.w, acc[3]);
        acc[4] = fmaf(xv, w1.x, acc[4]);
        acc[5] = fmaf(xv, w1.y, acc[5]);
        acc[6] = fmaf(xv, w1.z, acc[6]);
        acc[7] = fmaf(xv, w1.w, acc[7]);
    }

    float* hp = H + (size_t)(row0 + r) * DD + j;
    *reinterpret_cast<float4*>(hp)     = make_float4(acc[0], acc[1], acc[2], acc[3]);
    *reinterpret_cast<float4*>(hp + 4) = make_float4(acc[4], acc[5], acc[6], acc[7]);
}

// ---------------------------------------------------------------------------
// CSR gather, 1 warp/node, float2 per lane, 8-edge prefetched batches.
// rowptr[n] is the END of row n; start = rowptr[n-1] (0 for n=0).
// ---------------------------------------------------------------------------
__global__ void k_gather(const float* __restrict__ H, float* __restrict__ OUT,
                         const float* __restrict__ b, int do_relu) {
    int n = (blockIdx.x * blockDim.x + threadIdx.x) >> 5;
    if (n >= NN) return;
    int lane = threadIdx.x & 31;
    const float2* __restrict__ H2 = reinterpret_cast<const float2*>(H);

    int beg = (n == 0) ? 0 : g_rowptr[n - 1];
    int end = g_rowptr[n];

    float2 a0 = make_float2(0.f, 0.f), a1 = a0, a2 = a0, a3 = a0;

    int2 p[8];
#pragma unroll
    for (int j = 0; j < 8; j++)
        p[j] = (beg + j < end) ? g_epair[beg + j] : make_int2(0, 0);

    int e = beg;
    while (e + 8 <= end) {
        float2 f[8];
#pragma unroll
        for (int j = 0; j < 8; j++)
            f[j] = H2[((size_t)p[j].x << 5) + lane];

        int2 np[8];
#pragma unroll
        for (int j = 0; j < 8; j++)
            np[j] = (e + 8 + j < end) ? g_epair[e + 8 + j] : make_int2(0, 0);

#pragma unroll
        for (int j = 0; j < 8; j++) {
            float c = __int_as_float(p[j].y);
            float2* a = (j & 3) == 0 ? &a0 : (j & 3) == 1 ? &a1 : (j & 3) == 2 ? &a2 : &a3;
            a->x = fmaf(c, f[j].x, a->x);
            a->y = fmaf(c, f[j].y, a->y);
        }
#pragma unroll
        for (int j = 0; j < 8; j++) p[j] = np[j];
        e += 8;
    }

    int rem = end - e;
#pragma unroll
    for (int j = 0; j < 8; j++) {
        if (j < rem) {
            float2 f = H2[((size_t)p[j].x << 5) + lane];
            float c = __int_as_float(p[j].y);
            float2* a = (j & 3) == 0 ? &a0 : (j & 3) == 1 ? &a1 : (j & 3) == 2 ? &a2 : &a3;
            a->x = fmaf(c, f.x, a->x);
            a->y = fmaf(c, f.y, a->y);
        }
    }

    float s = g_dis[n];
    s = s * s;
    float2 hs = H2[((size_t)n << 5) + lane];
    float2 bv = reinterpret_cast<const float2*>(b)[lane];

    float ox = (a0.x + a1.x) + (a2.x + a3.x) + hs.x * s + bv.x;
    float oy = (a0.y + a1.y) + (a2.y + a3.y) + hs.y * s + bv.y;
    if (do_relu) { ox = fmaxf(ox, 0.f); oy = fmaxf(oy, 0.f); }
    reinterpret_cast<float2*>(OUT)[((size_t)n << 5) + lane] = make_float2(ox, oy);
}

// ---------------------------------------------------------------------------
// Launch (order chosen so k_gather is process launch #4 for ncu capture)
// ---------------------------------------------------------------------------
extern "C" void kernel_launch(void* const* d_in, const int* in_sizes, int n_in,
                              void* d_out, int out_size) {
    const float* x  = (const float*)d_in[0];
    const int*   ei = (const int*)d_in[1];
    const float* w  = (const float*)d_in[2];
    const float* W1 = (const float*)d_in[3];
    const float* b1 = (const float*)d_in[4];
    const float* W2 = (const float*)d_in[5];
    const float* b2 = (const float*)d_in[6];
    float* out = (float*)d_out;

    const int* src = ei;
    const int* dst = ei + EE;

    float* h_p;   cudaGetSymbolAddress((void**)&h_p,   g_h);
    float* agg_p; cudaGetSymbolAddress((void**)&agg_p, g_agg);

    const int T = 256;
    int bG = NN / 32;                          // 3125
    int bW = (NN * 32 + T - 1) / T;            // 12500 (1 warp/node)

    k_dummy<<<1, 32>>>();                      // #1
    k_gemm<<<bG, T>>>(x, W1, h_p);             // #2 (independent of CSR)
    k_build<<<BB, BT>>>(src, dst, w);          // #3 fused CSR build
    k_gather<<<bW, T>>>(h_p, agg_p, b1, 1);    // #4  <-- profiled
    k_gemm<<<bG, T>>>(agg_p, W2, h_p);         // #5
    k_gather<<<bW, T>>>(h_p, out, b2, 0);      // #6
}

// round 5
// speedup vs baseline: 1.2113x; 1.0710x over previous
#include <cuda_runtime.h>
#include <cuda_bf16.h>
#include <cstdint>

#define NN 100000
#define EE 1250000
#define DD 64
#define NB ((NN + 255) / 256)   // 391 scan blocks

// ---------------------------------------------------------------------------
// Scratch (__device__ globals; zero-initialized at load; self-restoring)
// ---------------------------------------------------------------------------
__device__ unsigned long long g_pack[NN];  // [63:48] count, [47:0] fixed-point weighted deg
__device__ float g_dis[NN];                // deg^{-1/2}
__device__ int   g_rowptr[NN];             // local-exclusive after scan1; local-inclusive after reorder
__device__ int   g_bsum[NB];               // block totals (scan1)
__device__ int   g_bsumx[NB];              // exclusive block offsets (scan2)
__device__ int2  g_epair[EE];              // (src, coef-bits), dst-grouped
__device__ float g_h[NN * DD];             // feature buffer A
__device__ float g_agg[NN * DD];           // feature buffer B

// ---------------------------------------------------------------------------
// Histogram: packed count + fixed-point weighted degree, 1 atomic per edge.
// g_pack is zero on entry (zeroed by scan1 of the previous run / initial load).
// ---------------------------------------------------------------------------
__global__ void k_hist(const int* __restrict__ dst, const float* __restrict__ w) {
    int e = blockIdx.x * blockDim.x + threadIdx.x;
    if (e < EE) {
        unsigned long long enc = (unsigned long long)(w[e] * 1099511627776.0f)  // w * 2^40
                               | (1ULL << 48);
        atomicAdd(&g_pack[dst[e]], enc);
    }
}

// ---------------------------------------------------------------------------
// scan1: read+clear pack, compute dis, block-local exclusive scan of counts.
// ---------------------------------------------------------------------------
__global__ void k_scan1() {
    __shared__ int sh[256];
    int t = threadIdx.x;
    int i = blockIdx.x * 256 + t;
    int cnt = 0;
    if (i < NN) {
        unsigned long long p = g_pack[i];
        g_pack[i] = 0ULL;                              // restore for next run
        cnt = (int)(p >> 48);
        float deg = (float)(p & ((1ULL << 48) - 1ULL)) * (1.0f / 1099511627776.0f);
        g_dis[i] = rsqrtf(deg + 1.0f);
    }
    sh[t] = cnt;
    __syncthreads();
    for (int off = 1; off < 256; off <<= 1) {
        int u = (t >= off) ? sh[t - off] : 0;
        __syncthreads();
        sh[t] += u;
        __syncthreads();
    }
    if (i < NN) g_rowptr[i] = sh[t] - cnt;             // local exclusive
    if (t == 255) g_bsum[blockIdx.x] = sh[255];
}

// scan2: exclusive scan of 391 block totals -> g_bsumx
__global__ void k_scan2() {
    __shared__ int sh[512];
    int t = threadIdx.x;
    int v = (t < NB) ? g_bsum[t] : 0;
    sh[t] = v;
    __syncthreads();
    for (int off = 1; off < 512; off <<= 1) {
        int u = (t >= off) ? sh[t - off] : 0;
        __syncthreads();
        sh[t] += u;
        __syncthreads();
    }
    if (t < NB) g_bsumx[t] = sh[t] - v;
}

// ---------------------------------------------------------------------------
// Reorder: pos = bsumx[d>>8] + atomicAdd(rowptr_local[d], 1). Fuses coef.
// After this, g_rowptr[n] = local INCLUSIVE count boundary.
// ---------------------------------------------------------------------------
__global__ void k_reorder(const int* __restrict__ src, const int* __restrict__ dst,
                          const float* __restrict__ w) {
    int e = blockIdx.x * blockDim.x + threadIdx.x;
    if (e >= EE) return;
    int s = src[e];
    int d = dst[e];
    float coef = g_dis[s] * w[e] * g_dis[d];
    int pos = g_bsumx[d >> 8] + atomicAdd(&g_rowptr[d], 1);
    g_epair[pos] = make_int2(s, __float_as_int(coef));
}

// ---------------------------------------------------------------------------
// GEMM: H[n][o] = sum_k X[n][k] * W[o][k]
// ---------------------------------------------------------------------------
__global__ void k_gemm(const float* __restrict__ X, const float* __restrict__ W,
                       float* __restrict__ H) {
    __shared__ float Ws[DD][DD];      // Ws[k][o] = W[o][k]
    __shared__ float Xs[32][DD + 1];

    int tid = threadIdx.x;
    int row0 = blockIdx.x * 32;

    for (int idx = tid; idx < DD * DD; idx += 256) {
        int o = idx / DD, k = idx % DD;
        Ws[k][o] = W[o * DD + k];
    }
    for (int idx = tid; idx < 32 * DD; idx += 256) {
        int r = idx / DD, k = idx % DD;
        Xs[r][k] = X[(size_t)(row0 + r) * DD + k];
    }
    __syncthreads();

    int r = tid >> 3;
    int j = (tid & 7) * 8;

    float acc[8];
#pragma unroll
    for (int i = 0; i < 8; i++) acc[i] = 0.0f;

#pragma unroll 8
    for (int k = 0; k < DD; k++) {
        float xv = Xs[r][k];
        float4 w0 = *reinterpret_cast<const float4*>(&Ws[k][j]);
        float4 w1 = *reinterpret_cast<const float4*>(&Ws[k][j + 4]);
        acc[0] = fmaf(xv, w0.x, acc[0]);
        acc[1] = fmaf(xv, w0.y, acc[1]);
        acc[2] = fmaf(xv, w0.z, acc[2]);
        acc[3] = fmaf(xv, w0.w, acc[3]);
        acc[4] = fmaf(xv, w1.x, acc[4]);
        acc[5] = fmaf(xv, w1.y, acc[5]);
        acc[6] = fmaf(xv, w1.z, acc[6]);
        acc[7] = fmaf(xv, w1.w, acc[7]);
    }

    float* hp = H + (size_t)(row0 + r) * DD + j;
    *reinterpret_cast<float4*>(hp)     = make_float4(acc[0], acc[1], acc[2], acc[3]);
    *reinterpret_cast<float4*>(hp + 4) = make_float4(acc[4], acc[5], acc[6], acc[7]);
}

// ---------------------------------------------------------------------------
// CSR gather, 1 warp/node, float2 per lane, 8-edge prefetched batches.
// Global row bounds reconstructed from local rowptr + block offsets.
// ---------------------------------------------------------------------------
__global__ void k_gather(const float* __restrict__ H, float* __restrict__ OUT,
                         const float* __restrict__ b, int do_relu) {
    int n = (blockIdx.x * blockDim.x + threadIdx.x) >> 5;
    if (n >= NN) return;
    int lane = threadIdx.x & 31;
    const float2* __restrict__ H2 = reinterpret_cast<const float2*>(H);

    int beg = (n == 0) ? 0 : (g_rowptr[n - 1] + g_bsumx[(n - 1) >> 8]);
    int end = g_rowptr[n] + g_bsumx[n >> 8];

    float2 a0 = make_float2(0.f, 0.f), a1 = a0, a2 = a0, a3 = a0;

    int2 p[8];
#pragma unroll
    for (int j = 0; j < 8; j++)
        p[j] = (beg + j < end) ? g_epair[beg + j] : make_int2(0, 0);

    int e = beg;
    while (e + 8 <= end) {
        float2 f[8];
#pragma unroll
        for (int j = 0; j < 8; j++)
            f[j] = H2[((size_t)p[j].x << 5) + lane];

        int2 np[8];
#pragma unroll
        for (int j = 0; j < 8; j++)
            np[j] = (e + 8 + j < end) ? g_epair[e + 8 + j] : make_int2(0, 0);

#pragma unroll
        for (int j = 0; j < 8; j++) {
            float c = __int_as_float(p[j].y);
            float2* a = (j & 3) == 0 ? &a0 : (j & 3) == 1 ? &a1 : (j & 3) == 2 ? &a2 : &a3;
            a->x = fmaf(c, f[j].x, a->x);
            a->y = fmaf(c, f[j].y, a->y);
        }
#pragma unroll
        for (int j = 0; j < 8; j++) p[j] = np[j];
        e += 8;
    }

    int rem = end - e;
#pragma unroll
    for (int j = 0; j < 8; j++) {
        if (j < rem) {
            float2 f = H2[((size_t)p[j].x << 5) + lane];
            float c = __int_as_float(p[j].y);
            float2* a = (j & 3) == 0 ? &a0 : (j & 3) == 1 ? &a1 : (j & 3) == 2 ? &a2 : &a3;
            a->x = fmaf(c, f.x, a->x);
            a->y = fmaf(c, f.y, a->y);
        }
    }

    float s = g_dis[n];
    s = s * s;
    float2 hs = H2[((size_t)n << 5) + lane];
    float2 bv = reinterpret_cast<const float2*>(b)[lane];

    float ox = (a0.x + a1.x) + (a2.x + a3.x) + hs.x * s + bv.x;
    float oy = (a0.y + a1.y) + (a2.y + a3.y) + hs.y * s + bv.y;
    if (do_relu) { ox = fmaxf(ox, 0.f); oy = fmaxf(oy, 0.f); }
    reinterpret_cast<float2*>(OUT)[((size_t)n << 5) + lane] = make_float2(ox, oy);
}

// ---------------------------------------------------------------------------
// Launch (k_reorder is process launch #4 -> profiled by ncu)
// ---------------------------------------------------------------------------
extern "C" void kernel_launch(void* const* d_in, const int* in_sizes, int n_in,
                              void* d_out, int out_size) {
    const float* x  = (const float*)d_in[0];
    const int*   ei = (const int*)d_in[1];
    const float* w  = (const float*)d_in[2];
    const float* W1 = (const float*)d_in[3];
    const float* b1 = (const float*)d_in[4];
    const float* W2 = (const float*)d_in[5];
    const float* b2 = (const float*)d_in[6];
    float* out = (float*)d_out;

    const int* src = ei;
    const int* dst = ei + EE;

    float* h_p;   cudaGetSymbolAddress((void**)&h_p,   g_h);
    float* agg_p; cudaGetSymbolAddress((void**)&agg_p, g_agg);

    const int T = 256;
    int bE = (EE + T - 1) / T;                 // 4883
    int bG = NN / 32;                          // 3125
    int bW = (NN * 32 + T - 1) / T;            // 12500 (1 warp/node)

    k_hist<<<bE, T>>>(dst, w);                 // #1
    k_scan1<<<NB, 256>>>();                    // #2 (also computes dis, clears pack)
    k_scan2<<<1, 512>>>();                     // #3
    k_reorder<<<bE, T>>>(src, dst, w);         // #4  <-- profiled
    k_gemm<<<bG, T>>>(x, W1, h_p);             // #5
    k_gather<<<bW, T>>>(h_p, agg_p, b1, 1);    // #6
    k_gemm<<<bG, T>>>(agg_p, W2, h_p);         // #7
    k_gather<<<bW, T>>>(h_p, out, b2, 0);      // #8
}